// round 11
// baseline (speedup 1.0000x reference)
#include <cuda_runtime.h>

// Problem constants (fixed by the dataset)
#define BATCH   8
#define LEN     4096
#define NK      128          // number of 2x2 rotor blocks
#define NSTATE  256          // state size = NK*2
#define M_TOTAL (BATCH*LEN)  // 32768 rows for both GEMMs
#define NCH     64           // scan chunks per sequence
#define LC      64           // chunk length (LEN/NCH), power of two
#define LOG2LC  6
#define OUT_Y   ((size_t)BATCH*LEN*NSTATE)  // y elements before new_state tail

// Scratch (device globals: no allocation allowed in kernel_launch)
__device__ float  g_uB[(size_t)M_TOTAL * NSTATE];   // u @ B
__device__ float  g_x [(size_t)M_TOTAL * NSTATE];   // scanned states
__device__ float2 g_h   [BATCH * NCH * NK];         // per-chunk local partials
__device__ float2 g_init[BATCH * NCH * NK];         // per-chunk entry states

// ---------------------------------------------------------------------------
// fp32 SIMT GEMM: C[M,N] = A[M,K] * B[K,N], 128x128 tile, 8x8 per thread
// ---------------------------------------------------------------------------
#define BM  128
#define BN  128
#define BKT 16
#define TM  8
#define TN  8

__global__ __launch_bounds__(256) void gemm_f32(
    const float* __restrict__ Am, const float* __restrict__ Bm,
    float* __restrict__ Cm, int M, int N, int Kd)
{
    __shared__ float As[BKT][BM];   // A stored transposed: As[k][m]
    __shared__ float Bs[BKT][BN];

    const int tid = threadIdx.x;
    const int tx  = tid & 15;     // column group (0..15)
    const int ty  = tid >> 4;     // row group    (0..15)
    const int blockRow = blockIdx.y * BM;
    const int blockCol = blockIdx.x * BN;

    float acc[TM][TN];
#pragma unroll
    for (int i = 0; i < TM; i++)
#pragma unroll
        for (int j = 0; j < TN; j++) acc[i][j] = 0.f;

    float ar[TM], br[TN];

    for (int k0 = 0; k0 < Kd; k0 += BKT) {
        // Load A tile: 128x16 floats = 512 float4; each thread loads 2
#pragma unroll
        for (int i = 0; i < 2; i++) {
            int f  = tid + i * 256;
            int r  = f >> 2;            // row within tile (0..127)
            int c4 = (f & 3) * 4;       // k offset (0,4,8,12)
            float4 v = *(const float4*)(Am + (size_t)(blockRow + r) * Kd + k0 + c4);
            As[c4 + 0][r] = v.x;
            As[c4 + 1][r] = v.y;
            As[c4 + 2][r] = v.z;
            As[c4 + 3][r] = v.w;
        }
        // Load B tile: 16x128 floats = 512 float4; each thread loads 2
#pragma unroll
        for (int i = 0; i < 2; i++) {
            int f  = tid + i * 256;
            int r  = f >> 5;            // k row (0..15)
            int c4 = (f & 31) * 4;      // col offset (0..124)
            *(float4*)(&Bs[r][c4]) =
                *(const float4*)(Bm + (size_t)(k0 + r) * N + blockCol + c4);
        }
        __syncthreads();

#pragma unroll
        for (int kk = 0; kk < BKT; kk++) {
            *(float4*)(&ar[0]) = *(const float4*)(&As[kk][ty * TM + 0]);
            *(float4*)(&ar[4]) = *(const float4*)(&As[kk][ty * TM + 4]);
            *(float4*)(&br[0]) = *(const float4*)(&Bs[kk][tx * TN + 0]);
            *(float4*)(&br[4]) = *(const float4*)(&Bs[kk][tx * TN + 4]);
#pragma unroll
            for (int i = 0; i < TM; i++)
#pragma unroll
                for (int j = 0; j < TN; j++)
                    acc[i][j] = fmaf(ar[i], br[j], acc[i][j]);
        }
        __syncthreads();
    }

#pragma unroll
    for (int i = 0; i < TM; i++) {
        float* crow = Cm + (size_t)(blockRow + ty * TM + i) * N + blockCol + tx * TN;
        *(float4*)(crow + 0) = make_float4(acc[i][0], acc[i][1], acc[i][2], acc[i][3]);
        *(float4*)(crow + 4) = make_float4(acc[i][4], acc[i][5], acc[i][6], acc[i][7]);
    }
}

// ---------------------------------------------------------------------------
// Scan phase 1: per-chunk local scan with zero initial state
// grid: (NCH, BATCH) x 128 threads (one rotor per thread)
// ---------------------------------------------------------------------------
__global__ __launch_bounds__(NK) void scan_partial(const float* __restrict__ A)
{
    const int k  = threadIdx.x;
    const int ch = blockIdx.x;
    const int b  = blockIdx.y;
    const float c = A[4 * k + 0];
    const float s = A[4 * k + 1];

    const float2* base = reinterpret_cast<const float2*>(g_uB)
                       + (size_t)(b * LEN + ch * LC) * NK + k;
    float zx = 0.f, zy = 0.f;
#pragma unroll 8
    for (int l = 0; l < LC; l++) {
        float2 w = base[(size_t)l * NK];
        float nx = fmaf(zx, c, fmaf(-zy, s, w.x));
        float ny = fmaf(zx, s, fmaf( zy, c, w.y));
        zx = nx; zy = ny;
    }
    g_h[((size_t)b * NCH + ch) * NK + k] = make_float2(zx, zy);
}

// ---------------------------------------------------------------------------
// Scan phase 2: sequential prefix across chunks (R^LC by double-prec squaring)
// grid: BATCH x 128 threads
// ---------------------------------------------------------------------------
__global__ __launch_bounds__(NK) void scan_prefix(
    const float* __restrict__ A, const float* __restrict__ x0)
{
    const int k = threadIdx.x;
    const int b = blockIdx.x;

    double cd = (double)A[4 * k + 0];
    double sd = (double)A[4 * k + 1];
#pragma unroll
    for (int i = 0; i < LOG2LC; i++) {      // (c,s) <- rotation angle doubling
        double nc = cd * cd - sd * sd;
        double ns = 2.0 * cd * sd;
        cd = nc; sd = ns;
    }
    const float Cc = (float)cd, Ss = (float)sd;

    float zx = x0[((size_t)b * NK + k) * 2 + 0];
    float zy = x0[((size_t)b * NK + k) * 2 + 1];
    for (int ch = 0; ch < NCH; ch++) {
        size_t idx = ((size_t)b * NCH + ch) * NK + k;
        g_init[idx] = make_float2(zx, zy);
        float2 h = g_h[idx];
        float nx = fmaf(zx, Cc, fmaf(-zy, Ss, h.x));
        float ny = fmaf(zx, Ss, fmaf( zy, Cc, h.y));
        zx = nx; zy = ny;
    }
}

// ---------------------------------------------------------------------------
// Scan phase 3: replay with correct entry states, write x and new_state
// grid: (NCH, BATCH) x 128 threads
// ---------------------------------------------------------------------------
__global__ __launch_bounds__(NK) void scan_replay(
    const float* __restrict__ A, float* __restrict__ out)
{
    const int k  = threadIdx.x;
    const int ch = blockIdx.x;
    const int b  = blockIdx.y;
    const float c = A[4 * k + 0];
    const float s = A[4 * k + 1];

    const size_t idx = ((size_t)b * NCH + ch) * NK + k;
    float2 z0 = g_init[idx];
    float zx = z0.x, zy = z0.y;

    const float2* src = reinterpret_cast<const float2*>(g_uB)
                      + (size_t)(b * LEN + ch * LC) * NK + k;
    float2* dst = reinterpret_cast<float2*>(g_x)
                + (size_t)(b * LEN + ch * LC) * NK + k;

#pragma unroll 8
    for (int l = 0; l < LC; l++) {
        float2 w = src[(size_t)l * NK];
        float nx = fmaf(zx, c, fmaf(-zy, s, w.x));
        float ny = fmaf(zx, s, fmaf( zy, c, w.y));
        zx = nx; zy = ny;
        dst[(size_t)l * NK] = make_float2(zx, zy);
    }
    if (ch == NCH - 1) {   // new_state = x[:, -1]
        out[OUT_Y + ((size_t)b * NK + k) * 2 + 0] = zx;
        out[OUT_Y + ((size_t)b * NK + k) * 2 + 1] = zy;
    }
}

// ---------------------------------------------------------------------------
// Launch: u@B -> scan (3 phases) -> x@C (+ new_state tail written in replay)
// ---------------------------------------------------------------------------
extern "C" void kernel_launch(void* const* d_in, const int* in_sizes, int n_in,
                              void* d_out, int out_size)
{
    const float* u  = (const float*)d_in[0];
    const float* x0 = (const float*)d_in[1];
    const float* A  = (const float*)d_in[2];
    const float* B  = (const float*)d_in[3];
    const float* C  = (const float*)d_in[4];
    float* out = (float*)d_out;
    (void)in_sizes; (void)n_in; (void)out_size;

    float *uBp = nullptr, *xp = nullptr;
    cudaGetSymbolAddress((void**)&uBp, g_uB);
    cudaGetSymbolAddress((void**)&xp,  g_x);

    dim3 gemm_grid(NSTATE / BN, M_TOTAL / BM);   // (2, 256)
    gemm_f32<<<gemm_grid, 256>>>(u, B, uBp, M_TOTAL, NSTATE, NSTATE);

    scan_partial<<<dim3(NCH, BATCH), NK>>>(A);
    scan_prefix<<<BATCH, NK>>>(A, x0);
    scan_replay<<<dim3(NCH, BATCH), NK>>>(A, out);

    gemm_f32<<<gemm_grid, 256>>>(xp, C, out, M_TOTAL, NSTATE, NSTATE);
}

// round 14
// speedup vs baseline: 2.1278x; 2.1278x over previous
#include <cuda_runtime.h>
#include <cstdint>

// ─── Problem constants ─────────────────────────────────────────────────────
#define BATCH   8
#define LEN     4096
#define NK      128
#define NSTATE  256
#define M_TOTAL (BATCH*LEN)
#define NCH     128          // scan chunks per sequence
#define LC      32           // chunk length
#define LOG2LC  5
#define OUT_Y   ((size_t)BATCH*LEN*NSTATE)

// ─── Scratch (device globals; no allocation allowed) ───────────────────────
__device__ float  g_uB[(size_t)M_TOTAL * NSTATE];
__device__ float  g_x [(size_t)M_TOTAL * NSTATE];
__device__ float2 g_h   [BATCH * NCH * NK];
__device__ float2 g_init[BATCH * NCH * NK];
__device__ float  g_Bt[NSTATE * NSTATE];     // B^T  (K-major [N,K])
__device__ float  g_Ct[NSTATE * NSTATE];     // C^T

// ─── TF32 mma.sync GEMM ────────────────────────────────────────────────────
// C[M,256] = A[M,256] @ Bt^T  (A row-major [M,K], Bt row-major [N,K])
// Tile 128x128x32, 256 threads = 8 warps (4 m-warps x 2 n-warps),
// warp tile 32x64 = 2x8 m16n8k8 fragments.
#define BM 128
#define BN 128
#define BK 32
#define KTILES (NSTATE / BK)          // 8
#define APAD 36                       // row stride in floats (conflict-free)
#define ABUF (BM * APAD)              // uints per A stage
#define BBUF (BN * APAD)
#define BOFF (2 * ABUF)               // B region starts after 2 A stages
#define SMEM_U_TOTAL (2 * ABUF + 2 * BBUF)                 // 18432 uints
#define SMEM_BYTES (SMEM_U_TOTAL * 4)                      // 73728 B

__device__ __forceinline__ uint32_t f2tf32(float x) {
    uint32_t r;
    asm("cvt.rna.tf32.f32 %0, %1;" : "=r"(r) : "f"(x));
    return r;
}

__device__ __forceinline__ void mma_tf32(float* c, const uint32_t* a, const uint32_t* b)
{
    asm volatile(
        "mma.sync.aligned.m16n8k8.row.col.f32.tf32.tf32.f32 "
        "{%0,%1,%2,%3}, {%4,%5,%6,%7}, {%8,%9}, {%0,%1,%2,%3};"
        : "+f"(c[0]), "+f"(c[1]), "+f"(c[2]), "+f"(c[3])
        : "r"(a[0]), "r"(a[1]), "r"(a[2]), "r"(a[3]), "r"(b[0]), "r"(b[1]));
}

__global__ __launch_bounds__(256) void gemm_tf32(
    const float* __restrict__ Am, const float* __restrict__ Bt,
    float* __restrict__ Cm)
{
    extern __shared__ uint32_t smem_u[];

    const int tid = threadIdx.x;
    const int wid = tid >> 5;
    const int lid = tid & 31;
    const int gid = lid >> 2;         // group 0..7
    const int tig = lid & 3;          // thread-in-group 0..3
    const int warpM = wid & 3;        // 0..3  (32-row slabs)
    const int warpN = wid >> 2;       // 0..1  (64-col slabs)
    const int blockRow = blockIdx.y * BM;
    const int blockCol = blockIdx.x * BN;

    const float* Arow = Am + (size_t)blockRow * NSTATE;
    const float* Brow = Bt + (size_t)blockCol * NSTATE;

    // Per-thread global-load mapping: 4 float4 per matrix per K-tile.
    // float4 slot f = tid + i*256 (0..1023): row = f>>3, quad = f&7.
    float c[2][8][4];
#pragma unroll
    for (int mf = 0; mf < 2; mf++)
#pragma unroll
        for (int nf = 0; nf < 8; nf++)
#pragma unroll
            for (int j = 0; j < 4; j++) c[mf][nf][j] = 0.f;

    // Prologue: load K-tile 0 straight into stage 0.
#pragma unroll
    for (int i = 0; i < 4; i++) {
        int f = tid + i * 256;
        int r = f >> 3, q = f & 7;
        float4 va = *(const float4*)(Arow + (size_t)r * NSTATE + q * 4);
        float4 vb = *(const float4*)(Brow + (size_t)r * NSTATE + q * 4);
        uint32_t* ap = &smem_u[(size_t)r * APAD + q * 4];
        uint32_t* bp = &smem_u[BOFF + (size_t)r * APAD + q * 4];
        ap[0] = f2tf32(va.x); ap[1] = f2tf32(va.y); ap[2] = f2tf32(va.z); ap[3] = f2tf32(va.w);
        bp[0] = f2tf32(vb.x); bp[1] = f2tf32(vb.y); bp[2] = f2tf32(vb.z); bp[3] = f2tf32(vb.w);
    }
    __syncthreads();

    for (int kt = 0; kt < KTILES; kt++) {
        const int cur = kt & 1;
        float4 pa[4], pb[4];
        if (kt + 1 < KTILES) {
#pragma unroll
            for (int i = 0; i < 4; i++) {
                int f = tid + i * 256;
                int r = f >> 3, q = f & 7;
                pa[i] = *(const float4*)(Arow + (size_t)r * NSTATE + (kt + 1) * BK + q * 4);
                pb[i] = *(const float4*)(Brow + (size_t)r * NSTATE + (kt + 1) * BK + q * 4);
            }
        }

        const uint32_t* As = smem_u + (size_t)cur * ABUF;
        const uint32_t* Bs = smem_u + BOFF + (size_t)cur * BBUF;
#pragma unroll
        for (int ks = 0; ks < 4; ks++) {
            const int k0 = ks * 8;
            uint32_t af[2][4];
#pragma unroll
            for (int mf = 0; mf < 2; mf++) {
                int r0 = warpM * 32 + mf * 16 + gid;
                af[mf][0] = As[(size_t)(r0    ) * APAD + k0 + tig    ];
                af[mf][1] = As[(size_t)(r0 + 8) * APAD + k0 + tig    ];
                af[mf][2] = As[(size_t)(r0    ) * APAD + k0 + tig + 4];
                af[mf][3] = As[(size_t)(r0 + 8) * APAD + k0 + tig + 4];
            }
            uint32_t bf[8][2];
#pragma unroll
            for (int nf = 0; nf < 8; nf++) {
                int n0 = warpN * 64 + nf * 8 + gid;
                bf[nf][0] = Bs[(size_t)n0 * APAD + k0 + tig    ];
                bf[nf][1] = Bs[(size_t)n0 * APAD + k0 + tig + 4];
            }
#pragma unroll
            for (int mf = 0; mf < 2; mf++)
#pragma unroll
                for (int nf = 0; nf < 8; nf++)
                    mma_tf32(c[mf][nf], af[mf], bf[nf]);
        }

        if (kt + 1 < KTILES) {
            const int nxt = (kt + 1) & 1;
            uint32_t* Asd = smem_u + (size_t)nxt * ABUF;
            uint32_t* Bsd = smem_u + BOFF + (size_t)nxt * BBUF;
#pragma unroll
            for (int i = 0; i < 4; i++) {
                int f = tid + i * 256;
                int r = f >> 3, q = f & 7;
                uint32_t* ap = &Asd[(size_t)r * APAD + q * 4];
                uint32_t* bp = &Bsd[(size_t)r * APAD + q * 4];
                ap[0] = f2tf32(pa[i].x); ap[1] = f2tf32(pa[i].y);
                ap[2] = f2tf32(pa[i].z); ap[3] = f2tf32(pa[i].w);
                bp[0] = f2tf32(pb[i].x); bp[1] = f2tf32(pb[i].y);
                bp[2] = f2tf32(pb[i].z); bp[3] = f2tf32(pb[i].w);
            }
            __syncthreads();
        }
    }

    // Epilogue: c0,c1 at (row, 2*tig), c2,c3 at (row+8, 2*tig)
#pragma unroll
    for (int mf = 0; mf < 2; mf++) {
        int row = blockRow + warpM * 32 + mf * 16 + gid;
#pragma unroll
        for (int nf = 0; nf < 8; nf++) {
            int col = blockCol + warpN * 64 + nf * 8 + tig * 2;
            *(float2*)(Cm + (size_t)row * NSTATE + col) =
                make_float2(c[mf][nf][0], c[mf][nf][1]);
            *(float2*)(Cm + (size_t)(row + 8) * NSTATE + col) =
                make_float2(c[mf][nf][2], c[mf][nf][3]);
        }
    }
}

// ─── 256x256 transpose (tiny, once per launch) ─────────────────────────────
__global__ __launch_bounds__(256) void transpose256(
    const float* __restrict__ in, float* __restrict__ out)
{
    int n = blockIdx.x;          // output row
    int k = threadIdx.x;         // output col
    out[n * 256 + k] = in[k * 256 + n];
}

// ─── Scan phase 1: per-chunk local scan (zero init) ────────────────────────
__global__ __launch_bounds__(NK) void scan_partial(const float* __restrict__ A)
{
    const int k  = threadIdx.x;
    const int ch = blockIdx.x;
    const int b  = blockIdx.y;
    const float c = A[4 * k + 0];
    const float s = A[4 * k + 1];

    const float2* base = reinterpret_cast<const float2*>(g_uB)
                       + (size_t)(b * LEN + ch * LC) * NK + k;
    float zx = 0.f, zy = 0.f;
#pragma unroll 8
    for (int l = 0; l < LC; l++) {
        float2 w = base[(size_t)l * NK];
        float nx = fmaf(zx, c, fmaf(-zy, s, w.x));
        float ny = fmaf(zx, s, fmaf( zy, c, w.y));
        zx = nx; zy = ny;
    }
    g_h[((size_t)b * NCH + ch) * NK + k] = make_float2(zx, zy);
}

// ─── Scan phase 2: cross-chunk prefix (R^LC via double-prec doubling) ──────
__global__ __launch_bounds__(NK) void scan_prefix(
    const float* __restrict__ A, const float* __restrict__ x0)
{
    const int k = threadIdx.x;
    const int b = blockIdx.x;

    double cd = (double)A[4 * k + 0];
    double sd = (double)A[4 * k + 1];
#pragma unroll
    for (int i = 0; i < LOG2LC; i++) {
        double nc = cd * cd - sd * sd;
        double ns = 2.0 * cd * sd;
        cd = nc; sd = ns;
    }
    const float Cc = (float)cd, Ss = (float)sd;

    float zx = x0[((size_t)b * NK + k) * 2 + 0];
    float zy = x0[((size_t)b * NK + k) * 2 + 1];
    for (int ch = 0; ch < NCH; ch++) {
        size_t idx = ((size_t)b * NCH + ch) * NK + k;
        g_init[idx] = make_float2(zx, zy);
        float2 h = g_h[idx];
        float nx = fmaf(zx, Cc, fmaf(-zy, Ss, h.x));
        float ny = fmaf(zx, Ss, fmaf( zy, Cc, h.y));
        zx = nx; zy = ny;
    }
}

// ─── Scan phase 3: replay, write x and new_state ───────────────────────────
__global__ __launch_bounds__(NK) void scan_replay(
    const float* __restrict__ A, float* __restrict__ out)
{
    const int k  = threadIdx.x;
    const int ch = blockIdx.x;
    const int b  = blockIdx.y;
    const float c = A[4 * k + 0];
    const float s = A[4 * k + 1];

    const size_t idx = ((size_t)b * NCH + ch) * NK + k;
    float2 z0 = g_init[idx];
    float zx = z0.x, zy = z0.y;

    const float2* src = reinterpret_cast<const float2*>(g_uB)
                      + (size_t)(b * LEN + ch * LC) * NK + k;
    float2* dst = reinterpret_cast<float2*>(g_x)
                + (size_t)(b * LEN + ch * LC) * NK + k;

#pragma unroll 8
    for (int l = 0; l < LC; l++) {
        float2 w = src[(size_t)l * NK];
        float nx = fmaf(zx, c, fmaf(-zy, s, w.x));
        float ny = fmaf(zx, s, fmaf( zy, c, w.y));
        zx = nx; zy = ny;
        dst[(size_t)l * NK] = make_float2(zx, zy);
    }
    if (ch == NCH - 1) {
        out[OUT_Y + ((size_t)b * NK + k) * 2 + 0] = zx;
        out[OUT_Y + ((size_t)b * NK + k) * 2 + 1] = zy;
    }
}

// ─── Launch ────────────────────────────────────────────────────────────────
extern "C" void kernel_launch(void* const* d_in, const int* in_sizes, int n_in,
                              void* d_out, int out_size)
{
    const float* u  = (const float*)d_in[0];
    const float* x0 = (const float*)d_in[1];
    const float* A  = (const float*)d_in[2];
    const float* B  = (const float*)d_in[3];
    const float* C  = (const float*)d_in[4];
    float* out = (float*)d_out;
    (void)in_sizes; (void)n_in; (void)out_size;

    float *uBp, *xp, *Btp, *Ctp;
    cudaGetSymbolAddress((void**)&uBp, g_uB);
    cudaGetSymbolAddress((void**)&xp,  g_x);
    cudaGetSymbolAddress((void**)&Btp, g_Bt);
    cudaGetSymbolAddress((void**)&Ctp, g_Ct);

    cudaFuncSetAttribute(gemm_tf32, cudaFuncAttributeMaxDynamicSharedMemorySize, SMEM_BYTES);

    transpose256<<<NSTATE, NSTATE>>>(B, Btp);
    transpose256<<<NSTATE, NSTATE>>>(C, Ctp);

    dim3 gemm_grid(NSTATE / BN, M_TOTAL / BM);     // (2, 256)
    gemm_tf32<<<gemm_grid, 256, SMEM_BYTES>>>(u, Btp, uBp);

    scan_partial<<<dim3(NCH, BATCH), NK>>>(A);
    scan_prefix<<<BATCH, NK>>>(A, x0);
    scan_replay<<<dim3(NCH, BATCH), NK>>>(A, out);

    gemm_tf32<<<gemm_grid, 256, SMEM_BYTES>>>(xp, Ctp, out);
}